// round 6
// baseline (speedup 1.0000x reference)
#include <cuda_runtime.h>
#include <cuda_bf16.h>

#define BINS 256
#define NCOPIES 16          // 2 sub-histograms per warp (selected by lane parity)
#define HIST_BLOCKS 1184    // 148 SMs x 8 blocks -> exactly one wave at occupancy 8
#define HIST_THREADS 256

// Scratch (device globals -> no allocation). Zero-initialized at module load;
// the last block resets them every launch, so every graph replay starts clean.
__device__ unsigned int g_hist[BINS];
__device__ unsigned int g_ticket;

__device__ __forceinline__ void bin_one(float x, unsigned int* hist) {
    // torch.histc over [-4,4]: x==4 -> last bin; outside ignored.
    // fmaf(x,32,128) == round((x+4)*32) bit-exact (power-of-2 scale commutes
    // with rounding), matching the reference arithmetic.
    if (x >= -4.0f && x <= 4.0f) {
        float t = fmaf(x, 32.0f, 128.0f);
        int idx = __float2int_rd(t);
        idx = min(idx, BINS - 1);
        atomicAdd(&hist[idx], 1u);
    }
}

__device__ __forceinline__ void bin4(float4 v, unsigned int* h) {
    bin_one(v.x, h);
    bin_one(v.y, h);
    bin_one(v.z, h);
    bin_one(v.w, h);
}

__global__ void __launch_bounds__(HIST_THREADS, 8)
hist_kernel(const float* __restrict__ x, long long n,
            float* __restrict__ out, int out_size) {
    __shared__ unsigned int sh[NCOPIES][BINS];
    __shared__ bool is_last;
    const int tid  = threadIdx.x;
    const int warp = tid >> 5;
    const int lane = tid & 31;
    // Per-thread histogram pointer: 2 copies per warp, split by lane parity.
    unsigned int* wh = sh[(warp << 1) | (lane & 1)];

    // Zero shared histograms
    #pragma unroll
    for (int i = tid; i < NCOPIES * BINS; i += HIST_THREADS)
        ((unsigned int*)sh)[i] = 0u;
    __syncthreads();

    const long long n4 = n >> 2;
    const float4* __restrict__ x4 = (const float4*)x;
    const long long stride = (long long)gridDim.x * HIST_THREADS;
    long long i = (long long)blockIdx.x * HIST_THREADS + tid;

    // Main loop: 4 independent LDG.128 front-batched per iteration (MLP_p1 = 4)
    for (; i + 3 * stride < n4; i += 4 * stride) {
        float4 a = x4[i];
        float4 b = x4[i + stride];
        float4 c = x4[i + 2 * stride];
        float4 d = x4[i + 3 * stride];
        bin4(a, wh);
        bin4(b, wh);
        bin4(c, wh);
        bin4(d, wh);
    }
    // Remainder float4s
    for (; i < n4; i += stride)
        bin4(x4[i], wh);

    // Scalar tail (n not multiple of 4) — block 0 only
    if (blockIdx.x == 0) {
        for (long long j = (n4 << 2) + tid; j < n; j += HIST_THREADS)
            bin_one(x[j], wh);
    }
    __syncthreads();

    // Reduce the copies, one gmem atomic per bin per block
    for (int b = tid; b < BINS; b += HIST_THREADS) {
        unsigned int s = 0;
        #pragma unroll
        for (int c = 0; c < NCOPIES; c++) s += sh[c][b];
        if (s) atomicAdd(&g_hist[b], s);
    }

    // Last-block-done protocol: final block writes the output and resets state.
    __threadfence();
    __syncthreads();
    if (tid == 0)
        is_last = (atomicAdd(&g_ticket, 1u) == (unsigned)gridDim.x - 1u);
    __syncthreads();

    if (is_last) {
        __threadfence();                 // make all blocks' g_hist atomics visible
        unsigned int v = g_hist[tid];
        g_hist[tid] = 0u;                // reset for next graph replay
        if (tid == 0) g_ticket = 0u;
        float fv = (float)v;
        // Reference returns (h, h): fill every 256-element chunk of out.
        for (int base = 0; base + tid < out_size; base += BINS)
            out[base + tid] = fv;
    }
}

extern "C" void kernel_launch(void* const* d_in, const int* in_sizes, int n_in,
                              void* d_out, int out_size) {
    const float* x = (const float*)d_in[0];
    long long n = (long long)in_sizes[0];
    float* out = (float*)d_out;

    hist_kernel<<<HIST_BLOCKS, HIST_THREADS>>>(x, n, out, out_size);
}

// round 7
// speedup vs baseline: 1.1022x; 1.1022x over previous
#include <cuda_runtime.h>
#include <cuda_bf16.h>

#define BINS 256
#define NCOPIES 16          // 2 sub-histograms per warp (selected by lane parity)
#define HIST_BLOCKS 1184    // 148 SMs x 8 blocks -> one wave at occupancy 8
#define HIST_THREADS 256

// Scratch (device globals -> no allocation). Zero-initialized at module load;
// the last block resets them every launch, so every graph replay starts clean.
__device__ unsigned int g_hist[BINS];
__device__ unsigned int g_ticket;

__device__ __forceinline__ void bin_one(float x, unsigned int* hist) {
    // torch.histc over [-4,4]: x==4 -> last bin; outside ignored; NaN ignored.
    // |x| <= 4  <=>  -4 <= x <= 4   (single FSETP, |x| is a free operand mod).
    // fmaf(x,32,128) == round((x+4)*32) bit-exact (power-of-2 scale commutes
    // with rounding): x==-4 -> 0, x==4 -> 256 -> min -> 255.
    if (fabsf(x) <= 4.0f) {
        float t = fmaf(x, 32.0f, 128.0f);
        int idx = __float2int_rd(t);
        idx = min(idx, BINS - 1);
        atomicAdd(&hist[idx], 1u);
    }
}

__device__ __forceinline__ void bin4(float4 v, unsigned int* h) {
    bin_one(v.x, h);
    bin_one(v.y, h);
    bin_one(v.z, h);
    bin_one(v.w, h);
}

__global__ void __launch_bounds__(HIST_THREADS, 8)
hist_kernel(const float* __restrict__ x, long long n,
            float* __restrict__ out, int out_size) {
    __shared__ unsigned int sh[NCOPIES][BINS];
    __shared__ bool is_last;
    const int tid  = threadIdx.x;
    const int warp = tid >> 5;
    const int lane = tid & 31;
    unsigned int* wh = sh[(warp << 1) | (lane & 1)];

    // Zero shared histograms
    #pragma unroll
    for (int i = tid; i < NCOPIES * BINS; i += HIST_THREADS)
        ((unsigned int*)sh)[i] = 0u;
    __syncthreads();

    const long long n4 = n >> 2;
    const float4* __restrict__ x4 = (const float4*)x;
    const long long stride = (long long)gridDim.x * HIST_THREADS;
    long long i = (long long)blockIdx.x * HIST_THREADS + tid;

    // Software-pipelined mainloop: prefetch next 2 float4 before binning the
    // current 2. Live set = 4 float4 (16 regs) -> still 32 regs, occ 8, but
    // every bin phase now runs with >=256B of loads in flight per warp.
    if (i + stride < n4) {
        float4 a = x4[i];
        float4 b = x4[i + stride];
        long long j = i + 2 * stride;
        for (; j + stride < n4; j += 2 * stride) {
            float4 c = x4[j];
            float4 d = x4[j + stride];
            bin4(a, wh);
            bin4(b, wh);
            a = c;
            b = d;
        }
        bin4(a, wh);
        bin4(b, wh);
        i = j;
    }
    // Remainder float4s
    for (; i < n4; i += stride)
        bin4(x4[i], wh);

    // Scalar tail (n not multiple of 4) — block 0 only
    if (blockIdx.x == 0) {
        for (long long j = (n4 << 2) + tid; j < n; j += HIST_THREADS)
            bin_one(x[j], wh);
    }
    __syncthreads();

    // Reduce the copies, one gmem atomic per bin per block
    for (int b = tid; b < BINS; b += HIST_THREADS) {
        unsigned int s = 0;
        #pragma unroll
        for (int c = 0; c < NCOPIES; c++) s += sh[c][b];
        if (s) atomicAdd(&g_hist[b], s);
    }

    // Last-block-done protocol: final block writes the output and resets state.
    __threadfence();
    __syncthreads();
    if (tid == 0)
        is_last = (atomicAdd(&g_ticket, 1u) == (unsigned)gridDim.x - 1u);
    __syncthreads();

    if (is_last) {
        __threadfence();                 // make all blocks' g_hist atomics visible
        unsigned int v = g_hist[tid];
        g_hist[tid] = 0u;                // reset for next graph replay
        if (tid == 0) g_ticket = 0u;
        float fv = (float)v;
        // Reference returns (h, h): fill every 256-element chunk of out.
        for (int base = 0; base + tid < out_size; base += BINS)
            out[base + tid] = fv;
    }
}

extern "C" void kernel_launch(void* const* d_in, const int* in_sizes, int n_in,
                              void* d_out, int out_size) {
    const float* x = (const float*)d_in[0];
    long long n = (long long)in_sizes[0];
    float* out = (float*)d_out;

    hist_kernel<<<HIST_BLOCKS, HIST_THREADS>>>(x, n, out, out_size);
}